// round 14
// baseline (speedup 1.0000x reference)
#include <cuda_runtime.h>
#include <cuda_bf16.h>

// Box_diamond: two-layer soft-AND over 8-wide bins.
// out[b,p] = 1/(1 - log prod_m( (s_m - W2[p,m]) / s_m )),
// s_m = 1 - log prod_{l: -2<=l-m<=3} (1 - x[..]*W1[p,l-m]),  p = 4g+j
// W1[p,d]=sigmoid(d*(t2-d)); window d in [-2,3] (verified rel_err ~3e-7).
// R14: warp-autonomous pipelines. Each warp owns 8 b-rows (2 groups of 4),
// stages through its PRIVATE double buffer with __syncwarp only (block
// barrier used once, for the shared t-tables). XOR-swizzled SMEM (pitch
// 144: conflict-free STS.128 + LDS.64 for the 2-rows-per-phase mapping),
// linear LDG.128, direct coalesced streaming stores, f32x2 packed math.

#define D_TOT   4096
#define P_TOT   512
#define NTH     256
#define PITCH   144          // floats; 72 u64 == 8 mod 16 -> phase-disjoint rows

typedef unsigned long long u64;

#define ONE2     0x3F8000003F800000ULL  // {1.0f, 1.0f}
#define NEGLN2_2 0xBF317218BF317218ULL  // {-ln2, -ln2}

__device__ __forceinline__ u64 fma2(u64 a, u64 b, u64 c) {
    u64 d; asm("fma.rn.f32x2 %0, %1, %2, %3;" : "=l"(d) : "l"(a), "l"(b), "l"(c)); return d;
}
__device__ __forceinline__ u64 mul2(u64 a, u64 b) {
    u64 d; asm("mul.rn.f32x2 %0, %1, %2;" : "=l"(d) : "l"(a), "l"(b)); return d;
}
__device__ __forceinline__ u64 pack2(float lo, float hi) {
    u64 d; asm("mov.b64 %0, {%1, %2};" : "=l"(d) : "f"(lo), "f"(hi)); return d;
}
__device__ __forceinline__ void unpack2(float& lo, float& hi, u64 v) {
    asm("mov.b64 {%0, %1}, %2;" : "=f"(lo), "=f"(hi) : "l"(v));
}
__device__ __forceinline__ float frcp(float v) {
    float r; asm("rcp.approx.f32 %0, %1;" : "=f"(r) : "f"(v)); return r;
}
__device__ __forceinline__ float fsigmoid(float z) {
    return frcp(1.0f + __expf(-z));
}
__device__ __forceinline__ float4 ldg128(const float* p) {
    float4 v;
    asm("ld.global.nc.v4.f32 {%0, %1, %2, %3}, [%4];"
        : "=f"(v.x), "=f"(v.y), "=f"(v.z), "=f"(v.w) : "l"(p));
    return v;
}
__device__ __forceinline__ void st_stream_f2(float* p, float a, float b) {
    asm volatile("st.global.cs.v2.f32 [%0], {%1, %2};" :: "l"(p), "f"(a), "f"(b));
}

__global__ __launch_bounds__(NTH, 5)
void box_diamond_kernel(const float* __restrict__ x,
                        const float* __restrict__ t0,
                        const float* __restrict__ t1,
                        const float* __restrict__ t2,
                        float* __restrict__ out) {
    // per-warp private staging: [warp][buf][row4][PITCH]
    __shared__ __align__(16) float xs[8][2][4][PITCH];   // 36.9 KB
    __shared__ float w1s[6][16];   // -W1 [d+2][p_local], d in [-2,3]
    __shared__ float w2s[8][16];   // 1-W2 [m][p_local]

    const int tid   = threadIdx.x;
    const int lane  = tid & 31;
    const int wid   = tid >> 5;
    const int by    = blockIdx.y;            // p-tile of 16
    const int pbase = by * 16;
    const int rb    = blockIdx.x * 64 + wid * 8;   // this warp's 8 rows

    // ---- t-parameter loads (registers; tables built from these) ----
    float rt0 = 0.f, rt1 = 0.f, rt2 = 0.f;
    const int pl_t = tid & 15;
    if (tid < 128) {
        rt0 = __ldg(t0 + pbase + pl_t);
        rt1 = __ldg(t1 + pbase + pl_t);
        rt2 = __ldg(t2 + pbase + pl_t);
    }

    // ---- LDG group 0 (rows rb..rb+3); lane = LINEAR chunk ----
    const float* src = x + (size_t)rb * D_TOT + (size_t)by * 128 + lane * 4;
    float4 v[4];
    #pragma unroll
    for (int it = 0; it < 4; it++)
        v[it] = ldg128(src + (size_t)it * D_TOT);

    // ---- build tables (pure MUFU; overlaps load flight) ----
    if (tid < 96) {               // -W1: 6d x 16p, d = (tid>>4) - 2
        int di = tid >> 4;
        float dd = (float)(di - 2);
        w1s[di][pl_t] = -fsigmoid(dd * (rt2 - dd));
    }
    if (tid < 128) {              // 1-W2: 8m x 16p
        int m  = tid >> 4;
        float lf = (float)m;
        float z1 = (lf - rt0) * (rt1 - lf);
        float z2 = (7.0f - rt2 - lf) * lf;
        w2s[m][pl_t] = 1.0f - fsigmoid(z1) * fsigmoid(z2);
    }
    __syncthreads();              // the ONLY block barrier (tables ready)

    // XOR-swizzled STS chunk: c' = g*8 + (l^g), g=lane>>3, l=lane&7
    const int csw = (lane & 24) | ((lane ^ (lane >> 3)) & 7);

    // compute-side mapping: lane = r*8 + sub (r = row within 4-group)
    const int r    = lane >> 3;              // 0..3
    const int sub  = lane & 7;               // p-pair (p_local = 2*sub)
    const int g    = sub >> 1;
    const int jp   = sub & 1;
    const int gbase = g * 32 + jp * 2;       // row-local float base

    u64 w1r[6];
    #pragma unroll
    for (int d = 0; d < 6; d++)
        w1r[d] = *reinterpret_cast<const u64*>(&w1s[d][sub * 2]);

    const float LN2 = 0.6931471805599453f;

    #pragma unroll
    for (int grp = 0; grp < 2; grp++) {
        // ---- STS current group into this warp's private buffer ----
        #pragma unroll
        for (int it = 0; it < 4; it++)
            *reinterpret_cast<float4*>(&xs[wid][grp][it][csw * 4]) = v[it];

        // ---- prefetch group 1 (in flight through group-0 compute) ----
        if (grp == 0) {
            #pragma unroll
            for (int it = 0; it < 4; it++)
                v[it] = ldg128(src + (size_t)(4 + it) * D_TOT);
        }

        __syncwarp();             // warp-local visibility of the STS

        // ---- snapshot: 8 conflict-free LDS.64 ----
        // float offset of (l, g, jp) = g*32 + ((l^g)<<2) + jp*2
        u64 nx[8];
        #pragma unroll
        for (int l = 0; l < 8; l++)
            nx[l] = *reinterpret_cast<const u64*>(
                &xs[wid][grp][r][gbase + ((l ^ g) << 2)]);

        // ---- compute: 8 m, window l-m in [-2, 3] ----
        u64 num = ONE2, den = ONE2;
        #pragma unroll
        for (int m = 0; m < 8; m++) {
            const int lo = (m - 2 < 0) ? 0 : m - 2;
            const int hi = (m + 3 > 7) ? 7 : m + 3;
            u64 pr = fma2(nx[lo], w1r[lo - m + 2], ONE2);   // 1 - x*W1
            #pragma unroll
            for (int l = lo + 1; l <= hi; l++)
                pr = mul2(pr, fma2(nx[l], w1r[l - m + 2], ONE2));
            float a0, a1;
            unpack2(a0, a1, pr);
            u64 lg  = pack2(__log2f(a0), __log2f(a1));
            u64 w2v = *reinterpret_cast<const u64*>(&w2s[m][sub * 2]);
            num = mul2(num, fma2(lg, NEGLN2_2, w2v));   // s - W2
            den = mul2(den, fma2(lg, NEGLN2_2, ONE2));  // s
        }

        float n0, n1, d0, d1;
        unpack2(n0, n1, num);
        unpack2(d0, d1, den);
        float o0 = frcp(fmaf(-LN2, __log2f(n0) - __log2f(d0), 1.0f));
        float o1 = frcp(fmaf(-LN2, __log2f(n1) - __log2f(d1), 1.0f));

        // ---- direct coalesced store (64B per b-row segment) ----
        int brow = rb + grp * 4 + r;
        st_stream_f2(out + (size_t)brow * P_TOT + pbase + sub * 2, o0, o1);
    }
}

extern "C" void kernel_launch(void* const* d_in, const int* in_sizes, int n_in,
                              void* d_out, int out_size) {
    const float* x  = (const float*)d_in[0];
    const float* t0 = (const float*)d_in[1];
    const float* t1 = (const float*)d_in[2];
    const float* t2 = (const float*)d_in[3];
    float* out = (float*)d_out;

    int B = in_sizes[0] / D_TOT;              // 4096
    dim3 grid(B / 64, P_TOT / 16);            // (64, 32) = 2048 blocks
    box_diamond_kernel<<<grid, NTH>>>(x, t0, t1, t2, out);
}

// round 15
// speedup vs baseline: 1.1173x; 1.1173x over previous
#include <cuda_runtime.h>
#include <cuda_bf16.h>

// Box_diamond: two-layer soft-AND over 8-wide bins.
// out[b,p] = 1/(1 - log prod_m( (s_m - W2[p,m]) / s_m )),
// s_m = 1 - log prod_{l: -2<=l-m<=3} (1 - x[..]*W1[p,l-m]),  p = 4g+j
// W1[p,d]=sigmoid(d*(t2-d)); window d in [-2,3] (verified rel_err ~3e-7).
// R15: fused 2-tile interleaved compute (2 independent dependency chains
// per warp -> lg2 latency of tile A hidden under FMA of tile B), shared
// per-m w2 LDS, occ-3 register budget. R12 datapath: XOR-swizzled SMEM
// (linear LDG.128, conflict-free STS/LDS), ONE barrier, coalesced st.cs.

#define D_TOT   4096
#define P_TOT   512
#define NTH     256
#define PITCH   144          // floats; 72 u64 == 8 mod 16

typedef unsigned long long u64;

#define ONE2     0x3F8000003F800000ULL  // {1.0f, 1.0f}
#define NEGLN2_2 0xBF317218BF317218ULL  // {-ln2, -ln2}

__device__ __forceinline__ u64 fma2(u64 a, u64 b, u64 c) {
    u64 d; asm("fma.rn.f32x2 %0, %1, %2, %3;" : "=l"(d) : "l"(a), "l"(b), "l"(c)); return d;
}
__device__ __forceinline__ u64 mul2(u64 a, u64 b) {
    u64 d; asm("mul.rn.f32x2 %0, %1, %2;" : "=l"(d) : "l"(a), "l"(b)); return d;
}
__device__ __forceinline__ u64 pack2(float lo, float hi) {
    u64 d; asm("mov.b64 %0, {%1, %2};" : "=l"(d) : "f"(lo), "f"(hi)); return d;
}
__device__ __forceinline__ void unpack2(float& lo, float& hi, u64 v) {
    asm("mov.b64 {%0, %1}, %2;" : "=f"(lo), "=f"(hi) : "l"(v));
}
__device__ __forceinline__ float frcp(float v) {
    float r; asm("rcp.approx.f32 %0, %1;" : "=f"(r) : "f"(v)); return r;
}
__device__ __forceinline__ float fsigmoid(float z) {
    return frcp(1.0f + __expf(-z));
}
__device__ __forceinline__ float4 ldg128(const float* p) {
    float4 v;
    asm("ld.global.nc.v4.f32 {%0, %1, %2, %3}, [%4];"
        : "=f"(v.x), "=f"(v.y), "=f"(v.z), "=f"(v.w) : "l"(p));
    return v;
}
__device__ __forceinline__ void st_stream_f2(float* p, float a, float b) {
    asm volatile("st.global.cs.v2.f32 [%0], {%1, %2};" :: "l"(p), "f"(a), "f"(b));
}

__global__ __launch_bounds__(NTH, 3)
void box_diamond_kernel(const float* __restrict__ x,
                        const float* __restrict__ t0,
                        const float* __restrict__ t1,
                        const float* __restrict__ t2,
                        float* __restrict__ out) {
    __shared__ __align__(16) float xs[2][32][PITCH];  // 36.9 KB, two tiles
    __shared__ float w1s[6][16];   // -W1 [d+2][p_local], d in [-2,3]
    __shared__ float w2s[8][16];   // 1-W2 [m][p_local]

    const int tid   = threadIdx.x;
    const int by    = blockIdx.y;           // p-tile of 16
    const int pbase = by * 16;
    const int b0    = blockIdx.x * 64;      // two consecutive 32-row tiles

    const int lane = tid & 31;
    const int w    = tid >> 5;

    // ---- t-parameter loads (registers; tables built from these) ----
    float rt0 = 0.f, rt1 = 0.f, rt2 = 0.f;
    const int pl_t = tid & 15;
    if (tid < 128) {
        rt0 = __ldg(t0 + pbase + pl_t);
        rt1 = __ldg(t1 + pbase + pl_t);
        rt2 = __ldg(t2 + pbase + pl_t);
    }

    // ---- LDG both tiles: lane = LINEAR chunk -> merged 128B phases ----
    const float* src = x + (size_t)b0 * D_TOT + (size_t)by * 128 + lane * 4;
    float4 v0[4], v1[4];
    #pragma unroll
    for (int it = 0; it < 4; it++)
        v0[it] = ldg128(src + (size_t)(it * 8 + w) * D_TOT);
    #pragma unroll
    for (int it = 0; it < 4; it++)
        v1[it] = ldg128(src + (size_t)(32 + it * 8 + w) * D_TOT);

    // ---- build tables (pure MUFU; overlaps load flight) ----
    if (tid < 96) {               // -W1: 6d x 16p, d = (tid>>4) - 2
        int di = tid >> 4;
        float dd = (float)(di - 2);
        w1s[di][pl_t] = -fsigmoid(dd * (rt2 - dd));
    }
    if (tid < 128) {              // 1-W2: 8m x 16p
        int m  = tid >> 4;
        float lf = (float)m;
        float z1 = (lf - rt0) * (rt1 - lf);
        float z2 = (7.0f - rt2 - lf) * lf;
        w2s[m][pl_t] = 1.0f - fsigmoid(z1) * fsigmoid(z2);
    }

    // ---- STS both tiles at XOR-swizzled chunk c' = g*8 + (l^g) ----
    const int csw = (lane & 24) | ((lane ^ (lane >> 3)) & 7);
    #pragma unroll
    for (int it = 0; it < 4; it++)
        *reinterpret_cast<float4*>(&xs[0][it * 8 + w][csw * 4]) = v0[it];
    #pragma unroll
    for (int it = 0; it < 4; it++)
        *reinterpret_cast<float4*>(&xs[1][it * 8 + w][csw * 4]) = v1[it];

    __syncthreads();               // the ONLY barrier

    // compute-side mapping: lane = b4*8 + sub
    const int b4   = lane >> 3;              // 0..3
    const int sub  = lane & 7;               // p-pair (p_local = 2*sub)
    const int row  = w * 4 + b4;             // 0..31 within tile
    const int g    = sub >> 1;
    const int jp   = sub & 1;
    const int gbase = g * 32 + jp * 2;       // row-local float base

    // ---- snapshot BOTH tiles (16 conflict-free LDS.64) ----
    u64 nxA[8], nxB[8];
    #pragma unroll
    for (int l = 0; l < 8; l++)
        nxA[l] = *reinterpret_cast<const u64*>(&xs[0][row][gbase + ((l ^ g) << 2)]);
    #pragma unroll
    for (int l = 0; l < 8; l++)
        nxB[l] = *reinterpret_cast<const u64*>(&xs[1][row][gbase + ((l ^ g) << 2)]);

    u64 w1r[6];
    #pragma unroll
    for (int d = 0; d < 6; d++)
        w1r[d] = *reinterpret_cast<const u64*>(&w1s[d][sub * 2]);

    const float LN2 = 0.6931471805599453f;

    // ---- fused interleaved m-loop: two independent chains per warp ----
    u64 numA = ONE2, denA = ONE2, numB = ONE2, denB = ONE2;
    #pragma unroll
    for (int m = 0; m < 8; m++) {
        const int lo = (m - 2 < 0) ? 0 : m - 2;
        const int hi = (m + 3 > 7) ? 7 : m + 3;
        u64 prA = fma2(nxA[lo], w1r[lo - m + 2], ONE2);
        u64 prB = fma2(nxB[lo], w1r[lo - m + 2], ONE2);
        #pragma unroll
        for (int l = lo + 1; l <= hi; l++) {
            prA = mul2(prA, fma2(nxA[l], w1r[l - m + 2], ONE2));
            prB = mul2(prB, fma2(nxB[l], w1r[l - m + 2], ONE2));
        }
        float a0, a1, b0f, b1f;
        unpack2(a0, a1, prA);
        unpack2(b0f, b1f, prB);
        u64 lgA = pack2(__log2f(a0), __log2f(a1));
        u64 lgB = pack2(__log2f(b0f), __log2f(b1f));
        u64 w2v = *reinterpret_cast<const u64*>(&w2s[m][sub * 2]);  // shared
        numA = mul2(numA, fma2(lgA, NEGLN2_2, w2v));   // s - W2
        denA = mul2(denA, fma2(lgA, NEGLN2_2, ONE2));  // s
        numB = mul2(numB, fma2(lgB, NEGLN2_2, w2v));
        denB = mul2(denB, fma2(lgB, NEGLN2_2, ONE2));
    }

    // ---- epilogues (interleaved; 8 lg2 + 4 rcp) ----
    float na0, na1, da0, da1, nb0, nb1, db0, db1;
    unpack2(na0, na1, numA); unpack2(da0, da1, denA);
    unpack2(nb0, nb1, numB); unpack2(db0, db1, denB);
    float oA0 = frcp(fmaf(-LN2, __log2f(na0) - __log2f(da0), 1.0f));
    float oA1 = frcp(fmaf(-LN2, __log2f(na1) - __log2f(da1), 1.0f));
    float oB0 = frcp(fmaf(-LN2, __log2f(nb0) - __log2f(db0), 1.0f));
    float oB1 = frcp(fmaf(-LN2, __log2f(nb1) - __log2f(db1), 1.0f));

    // ---- direct coalesced stores (64B per b-row segment) ----
    float* obase = out + (size_t)(b0 + row) * P_TOT + pbase + sub * 2;
    st_stream_f2(obase, oA0, oA1);
    st_stream_f2(obase + (size_t)32 * P_TOT, oB0, oB1);
}

extern "C" void kernel_launch(void* const* d_in, const int* in_sizes, int n_in,
                              void* d_out, int out_size) {
    const float* x  = (const float*)d_in[0];
    const float* t0 = (const float*)d_in[1];
    const float* t1 = (const float*)d_in[2];
    const float* t2 = (const float*)d_in[3];
    float* out = (float*)d_out;

    int B = in_sizes[0] / D_TOT;              // 4096
    dim3 grid(B / 64, P_TOT / 16);            // (64, 32) = 2048 blocks
    box_diamond_kernel<<<grid, NTH>>>(x, t0, t1, t2, out);
}

// round 16
// speedup vs baseline: 1.1215x; 1.0037x over previous
#include <cuda_runtime.h>
#include <cuda_bf16.h>

// Box_diamond: two-layer soft-AND over 8-wide bins.
// out[b,p] = 1/(1 - log prod_m( (s_m - W2[p,m]) / s_m )),
// s_m = 1 - log prod_{l: -2<=l-m<=3} (1 - x[..]*W1[p,l-m]),  p = 4g+j
// W1[p,d]=sigmoid(d*(t2-d)); window d in [-2,3] (verified rel_err ~3e-7).
// R16: R15's fused 2-chain compute at occupancy 4. v-register reuse (LDG
// tile0 -> STS0 -> LDG tile1 into same regs) keeps peak ~60 regs; snapshots
// interleaved with STS1 so tile-B latency hides under resident blocks.
// XOR-swizzled SMEM (linear LDG.128, conflict-free STS/LDS), coalesced st.cs.

#define D_TOT   4096
#define P_TOT   512
#define NTH     256
#define PITCH   144          // floats; 72 u64 == 8 mod 16

typedef unsigned long long u64;

#define ONE2     0x3F8000003F800000ULL  // {1.0f, 1.0f}
#define NEGLN2_2 0xBF317218BF317218ULL  // {-ln2, -ln2}

__device__ __forceinline__ u64 fma2(u64 a, u64 b, u64 c) {
    u64 d; asm("fma.rn.f32x2 %0, %1, %2, %3;" : "=l"(d) : "l"(a), "l"(b), "l"(c)); return d;
}
__device__ __forceinline__ u64 mul2(u64 a, u64 b) {
    u64 d; asm("mul.rn.f32x2 %0, %1, %2;" : "=l"(d) : "l"(a), "l"(b)); return d;
}
__device__ __forceinline__ u64 pack2(float lo, float hi) {
    u64 d; asm("mov.b64 %0, {%1, %2};" : "=l"(d) : "f"(lo), "f"(hi)); return d;
}
__device__ __forceinline__ void unpack2(float& lo, float& hi, u64 v) {
    asm("mov.b64 {%0, %1}, %2;" : "=f"(lo), "=f"(hi) : "l"(v));
}
__device__ __forceinline__ float frcp(float v) {
    float r; asm("rcp.approx.f32 %0, %1;" : "=f"(r) : "f"(v)); return r;
}
__device__ __forceinline__ float fsigmoid(float z) {
    return frcp(1.0f + __expf(-z));
}
__device__ __forceinline__ float4 ldg128(const float* p) {
    float4 v;
    asm("ld.global.nc.v4.f32 {%0, %1, %2, %3}, [%4];"
        : "=f"(v.x), "=f"(v.y), "=f"(v.z), "=f"(v.w) : "l"(p));
    return v;
}
__device__ __forceinline__ void st_stream_f2(float* p, float a, float b) {
    asm volatile("st.global.cs.v2.f32 [%0], {%1, %2};" :: "l"(p), "f"(a), "f"(b));
}

__global__ __launch_bounds__(NTH, 4)
void box_diamond_kernel(const float* __restrict__ x,
                        const float* __restrict__ t0,
                        const float* __restrict__ t1,
                        const float* __restrict__ t2,
                        float* __restrict__ out) {
    __shared__ __align__(16) float xs[2][32][PITCH];  // 36.9 KB, two tiles
    __shared__ float w1s[6][16];   // -W1 [d+2][p_local], d in [-2,3]
    __shared__ float w2s[8][16];   // 1-W2 [m][p_local]

    const int tid   = threadIdx.x;
    const int by    = blockIdx.y;           // p-tile of 16
    const int pbase = by * 16;
    const int b0    = blockIdx.x * 64;      // two consecutive 32-row tiles

    const int lane = tid & 31;
    const int w    = tid >> 5;

    // ---- t-parameter loads (registers; tables built from these) ----
    float rt0 = 0.f, rt1 = 0.f, rt2 = 0.f;
    const int pl_t = tid & 15;
    if (tid < 128) {
        rt0 = __ldg(t0 + pbase + pl_t);
        rt1 = __ldg(t1 + pbase + pl_t);
        rt2 = __ldg(t2 + pbase + pl_t);
    }

    // ---- LDG tile 0 (16 regs; tile 1 reuses them) ----
    const float* src = x + (size_t)b0 * D_TOT + (size_t)by * 128 + lane * 4;
    float4 v[4];
    #pragma unroll
    for (int it = 0; it < 4; it++)
        v[it] = ldg128(src + (size_t)(it * 8 + w) * D_TOT);

    // ---- build tables (pure MUFU; overlaps load flight) ----
    if (tid < 96) {               // -W1: 6d x 16p, d = (tid>>4) - 2
        int di = tid >> 4;
        float dd = (float)(di - 2);
        w1s[di][pl_t] = -fsigmoid(dd * (rt2 - dd));
    }
    if (tid < 128) {              // 1-W2: 8m x 16p
        int m  = tid >> 4;
        float lf = (float)m;
        float z1 = (lf - rt0) * (rt1 - lf);
        float z2 = (7.0f - rt2 - lf) * lf;
        w2s[m][pl_t] = 1.0f - fsigmoid(z1) * fsigmoid(z2);
    }

    // XOR-swizzled STS chunk: c' = g*8 + (l^g), g=lane>>3, l=lane&7
    const int csw = (lane & 24) | ((lane ^ (lane >> 3)) & 7);

    // ---- STS tile 0, then LDG tile 1 into the SAME registers ----
    #pragma unroll
    for (int it = 0; it < 4; it++)
        *reinterpret_cast<float4*>(&xs[0][it * 8 + w][csw * 4]) = v[it];
    #pragma unroll
    for (int it = 0; it < 4; it++)
        v[it] = ldg128(src + (size_t)(32 + it * 8 + w) * D_TOT);

    __syncthreads();               // xs[0] + tables ready

    // compute-side mapping: lane = b4*8 + sub
    const int b4   = lane >> 3;              // 0..3
    const int sub  = lane & 7;               // p-pair (p_local = 2*sub)
    const int row  = w * 4 + b4;             // 0..31 within tile
    const int g    = sub >> 1;
    const int jp   = sub & 1;
    const int gbase = g * 32 + jp * 2;       // row-local float base

    // ---- snapshot tile A (8 conflict-free LDS.64) ----
    u64 nxA[8];
    #pragma unroll
    for (int l = 0; l < 8; l++)
        nxA[l] = *reinterpret_cast<const u64*>(&xs[0][row][gbase + ((l ^ g) << 2)]);

    u64 w1r[6];
    #pragma unroll
    for (int d = 0; d < 6; d++)
        w1r[d] = *reinterpret_cast<const u64*>(&w1s[d][sub * 2]);

    // ---- STS tile 1 (v dead afterwards; stall covered by resident blocks) ----
    #pragma unroll
    for (int it = 0; it < 4; it++)
        *reinterpret_cast<float4*>(&xs[1][it * 8 + w][csw * 4]) = v[it];

    __syncthreads();               // xs[1] ready

    // ---- snapshot tile B ----
    u64 nxB[8];
    #pragma unroll
    for (int l = 0; l < 8; l++)
        nxB[l] = *reinterpret_cast<const u64*>(&xs[1][row][gbase + ((l ^ g) << 2)]);

    const float LN2 = 0.6931471805599453f;

    // ---- fused interleaved m-loop: two independent chains per warp ----
    u64 numA = ONE2, denA = ONE2, numB = ONE2, denB = ONE2;
    #pragma unroll
    for (int m = 0; m < 8; m++) {
        const int lo = (m - 2 < 0) ? 0 : m - 2;
        const int hi = (m + 3 > 7) ? 7 : m + 3;
        u64 prA = fma2(nxA[lo], w1r[lo - m + 2], ONE2);
        u64 prB = fma2(nxB[lo], w1r[lo - m + 2], ONE2);
        #pragma unroll
        for (int l = lo + 1; l <= hi; l++) {
            prA = mul2(prA, fma2(nxA[l], w1r[l - m + 2], ONE2));
            prB = mul2(prB, fma2(nxB[l], w1r[l - m + 2], ONE2));
        }
        float a0, a1, b0f, b1f;
        unpack2(a0, a1, prA);
        unpack2(b0f, b1f, prB);
        u64 lgA = pack2(__log2f(a0), __log2f(a1));
        u64 lgB = pack2(__log2f(b0f), __log2f(b1f));
        u64 w2v = *reinterpret_cast<const u64*>(&w2s[m][sub * 2]);  // shared
        numA = mul2(numA, fma2(lgA, NEGLN2_2, w2v));   // s - W2
        denA = mul2(denA, fma2(lgA, NEGLN2_2, ONE2));  // s
        numB = mul2(numB, fma2(lgB, NEGLN2_2, w2v));
        denB = mul2(denB, fma2(lgB, NEGLN2_2, ONE2));
    }

    // ---- epilogues (8 lg2 + 4 rcp) ----
    float na0, na1, da0, da1, nb0, nb1, db0, db1;
    unpack2(na0, na1, numA); unpack2(da0, da1, denA);
    unpack2(nb0, nb1, numB); unpack2(db0, db1, denB);
    float oA0 = frcp(fmaf(-LN2, __log2f(na0) - __log2f(da0), 1.0f));
    float oA1 = frcp(fmaf(-LN2, __log2f(na1) - __log2f(da1), 1.0f));
    float oB0 = frcp(fmaf(-LN2, __log2f(nb0) - __log2f(db0), 1.0f));
    float oB1 = frcp(fmaf(-LN2, __log2f(nb1) - __log2f(db1), 1.0f));

    // ---- direct coalesced stores (64B per b-row segment) ----
    float* obase = out + (size_t)(b0 + row) * P_TOT + pbase + sub * 2;
    st_stream_f2(obase, oA0, oA1);
    st_stream_f2(obase + (size_t)32 * P_TOT, oB0, oB1);
}

extern "C" void kernel_launch(void* const* d_in, const int* in_sizes, int n_in,
                              void* d_out, int out_size) {
    const float* x  = (const float*)d_in[0];
    const float* t0 = (const float*)d_in[1];
    const float* t1 = (const float*)d_in[2];
    const float* t2 = (const float*)d_in[3];
    float* out = (float*)d_out;

    int B = in_sizes[0] / D_TOT;              // 4096
    dim3 grid(B / 64, P_TOT / 16);            // (64, 32) = 2048 blocks
    box_diamond_kernel<<<grid, NTH>>>(x, t0, t1, t2, out);
}